// round 7
// baseline (speedup 1.0000x reference)
#include <cuda_runtime.h>
#include <cstdint>

// out = noised + 0.1f * noise   (elementwise, fp32)
// N = 64*3*512*512 = 50,331,648 -> n8 = 6,291,456 (divisible by 256)
// R4 (float4, simple) = 88.9us bench / 82.3us kernel, 6.83 TB/s (86.2% DRAM).
// R5 (MLP batching) regressed -> we are DRAM-controller-bound, not latency-bound.
// R6: 256-bit ld/st (sm_100a+ v8) — halve wavefront count, bigger aligned bursts.

__device__ __forceinline__ void ldg_v8_nc(const float* __restrict__ p, float v[8]) {
    unsigned r0, r1, r2, r3, r4, r5, r6, r7;
    asm volatile("ld.global.nc.v8.b32 {%0,%1,%2,%3,%4,%5,%6,%7}, [%8];"
                 : "=r"(r0), "=r"(r1), "=r"(r2), "=r"(r3),
                   "=r"(r4), "=r"(r5), "=r"(r6), "=r"(r7)
                 : "l"(p));
    v[0] = __uint_as_float(r0); v[1] = __uint_as_float(r1);
    v[2] = __uint_as_float(r2); v[3] = __uint_as_float(r3);
    v[4] = __uint_as_float(r4); v[5] = __uint_as_float(r5);
    v[6] = __uint_as_float(r6); v[7] = __uint_as_float(r7);
}

__device__ __forceinline__ void stg_v8_cs(float* __restrict__ p, const float v[8]) {
    asm volatile("st.global.cs.v8.b32 [%0], {%1,%2,%3,%4,%5,%6,%7,%8};"
                 :: "l"(p),
                    "r"(__float_as_uint(v[0])), "r"(__float_as_uint(v[1])),
                    "r"(__float_as_uint(v[2])), "r"(__float_as_uint(v[3])),
                    "r"(__float_as_uint(v[4])), "r"(__float_as_uint(v[5])),
                    "r"(__float_as_uint(v[6])), "r"(__float_as_uint(v[7]))
                 : "memory");
}

__global__ void __launch_bounds__(256)
gaussian_noise_add_v8(const float* __restrict__ noised,
                      const float* __restrict__ noise,
                      float* __restrict__ out,
                      int n8)
{
    int i = blockIdx.x * blockDim.x + threadIdx.x;
    if (i < n8) {
        long long off = (long long)i * 8;
        float a[8], b[8], r[8];
        ldg_v8_nc(noised + off, a);
        ldg_v8_nc(noise + off, b);
#pragma unroll
        for (int j = 0; j < 8; j++)
            r[j] = fmaf(0.1f, b[j], a[j]);
        stg_v8_cs(out + off, r);
    }
}

// Scalar tail for n not divisible by 8 (not launched for this shape).
__global__ void gaussian_noise_tail_kernel(const float* __restrict__ noised,
                                           const float* __restrict__ noise,
                                           float* __restrict__ out,
                                           int start, int n)
{
    int i = start + blockIdx.x * blockDim.x + threadIdx.x;
    if (i < n) {
        out[i] = fmaf(0.1f, noise[i], noised[i]);
    }
}

extern "C" void kernel_launch(void* const* d_in, const int* in_sizes, int n_in,
                              void* d_out, int out_size)
{
    const float* noised = (const float*)d_in[0];
    const float* noise  = (const float*)d_in[1];
    float* out = (float*)d_out;
    int n = in_sizes[0];

    int n8 = n >> 3;
    if (n8 > 0) {
        const int threads = 256;
        int blocks = (n8 + threads - 1) / threads;
        gaussian_noise_add_v8<<<blocks, threads>>>(noised, noise, out, n8);
    }
    int rem = n - (n8 << 3);
    if (rem > 0) {
        gaussian_noise_tail_kernel<<<1, 256>>>(noised, noise, out, n8 << 3, n);
    }
}